// round 10
// baseline (speedup 1.0000x reference)
#include <cuda_runtime.h>
#include <cuda_fp16.h>
#include <math.h>
#include <stdint.h>

#define NPED  128
#define HD    64
#define NOUT  64
#define NROWS 4096
#define YC    4096      // Y columns = 64 cells * 64 out

// ---- scratch (no allocs allowed) ----
__device__ __align__(256) __half g_Y16[(size_t)NROWS * YC];    // 32 MB
__device__ __align__(256) __half g_W16[64 * YC];               // Wr: [h][c*64+o]
__device__ __align__(256) __half g_H16[NROWS * HD];            // hs fp16
__device__ float g_stat[128];                                  // [0:64) sum, [64:128) sumsq
__device__ float g_scale[NOUT];
__device__ float g_shift[NOUT];

// ---------------- helpers ----------------
__device__ __forceinline__ uint32_t smem_u32(const void* p) {
    uint32_t a;
    asm("{ .reg .u64 t; cvta.to.shared.u64 t, %1; cvt.u32.u64 %0, t; }" : "=r"(a) : "l"(p));
    return a;
}
__device__ __forceinline__ void cpa16(uint32_t dst, const void* src) {
    asm volatile("cp.async.cg.shared.global [%0], [%1], 16;" :: "r"(dst), "l"(src));
}
__device__ __forceinline__ void cp_commit() {
    asm volatile("cp.async.commit_group;" ::: "memory");
}
__device__ __forceinline__ void cp_wait1() {
    asm volatile("cp.async.wait_group 1;" ::: "memory");
}
__device__ __forceinline__ void cp_wait0() {
    asm volatile("cp.async.wait_group 0;" ::: "memory");
}
__device__ __forceinline__ void ldsm_x4(uint32_t* a, uint32_t addr) {
    asm volatile("ldmatrix.sync.aligned.m8n8.x4.shared.b16 {%0,%1,%2,%3}, [%4];"
                 : "=r"(a[0]), "=r"(a[1]), "=r"(a[2]), "=r"(a[3]) : "r"(addr));
}
__device__ __forceinline__ void ldsm_x4t(uint32_t* b, uint32_t addr) {
    asm volatile("ldmatrix.sync.aligned.m8n8.x4.trans.shared.b16 {%0,%1,%2,%3}, [%4];"
                 : "=r"(b[0]), "=r"(b[1]), "=r"(b[2]), "=r"(b[3]) : "r"(addr));
}
__device__ __forceinline__ void mma16816(float* d, const uint32_t* a, const uint32_t* b) {
    asm volatile("mma.sync.aligned.m16n8k16.row.col.f32.f16.f16.f32 "
                 "{%0,%1,%2,%3}, {%4,%5,%6,%7}, {%8,%9}, {%0,%1,%2,%3};"
                 : "+f"(d[0]), "+f"(d[1]), "+f"(d[2]), "+f"(d[3])
                 : "r"(a[0]), "r"(a[1]), "r"(a[2]), "r"(a[3]), "r"(b[0]), "r"(b[1]));
}

// ---------------------------------------------------------------------------
// Prep: blocks [0,1024) convert W -> g_W16 (transposed layout); blocks
// [1024,1280) convert hs -> g_H16. Block 0 also zeroes the stat buffer.
// ---------------------------------------------------------------------------
__global__ void prep_kernel(const float* __restrict__ W, const float* __restrict__ hs) {
    const int b = blockIdx.x, tid = threadIdx.x;
    if (b == 0 && tid < 128) g_stat[tid] = 0.0f;
    if (b < 1024) {
        const int e = b * 256 + tid;                 // 262144 total
        const int widx = ((e >> 6) & 63) * YC + (e >> 12) * 64 + (e & 63);
        g_W16[widx] = __float2half_rn(W[e]);
    } else {
        const int e4 = (b - 1024) * 256 + tid;       // 65536 float4 groups
        const float4 v = ((const float4*)hs)[e4];
        __half2 a = __floats2half2_rn(v.x, v.y);
        __half2 c = __floats2half2_rn(v.z, v.w);
        uint2 w;
        w.x = *(uint32_t*)&a;
        w.y = *(uint32_t*)&c;
        ((uint2*)g_H16)[e4] = w;
    }
}

// ---------------------------------------------------------------------------
// GEMM: Y[4096, 4096] = hs16[4096, 64] @ W16[64, 4096], fp32 accum HMMA.
// Grid 256 = 32 mb x 8 ng. CTA: 256 threads, A stripe [128 x 64] loaded once,
// iterates 4 N-tiles of 128 with double-buffered cp.async B loads.
// ---------------------------------------------------------------------------
__global__ void __launch_bounds__(256) gemm_kernel() {
    __shared__ __align__(16) __half sA[128 * 64];           // 16 KB
    __shared__ __align__(16) __half sB[2][2][64 * 64];      // 32 KB: [buf][half]

    const int tid = threadIdx.x, lane = tid & 31, w = tid >> 5;
    const int wm = w & 3, wn = w >> 2;
    const int mb = blockIdx.x >> 3, ng = blockIdx.x & 7;
    const int m0 = mb * 128;

    const uint32_t aBase = smem_u32(sA);
    const uint32_t bBase = smem_u32(sB);

    // A: 1024 uint4, 4 per thread, swizzled.
    #pragma unroll
    for (int u = 0; u < 4; ++u) {
        const int idx = u * 256 + tid;
        const int r = idx >> 3, chunk = idx & 7;
        cpa16(aBase + r * 128 + ((chunk ^ (r & 7)) * 16),
              g_H16 + (size_t)(m0 + r) * HD + chunk * 8);
    }

    auto issueB = [&](int t, int buf) {
        const int n0 = ng * 512 + t * 128;
        #pragma unroll
        for (int u = 0; u < 4; ++u) {
            const int idx = u * 256 + tid;
            const int h = idx >> 9, i2 = idx & 511;
            const int r = i2 >> 3, chunk = i2 & 7;
            cpa16(bBase + buf * 16384 + h * 8192 + r * 128 + ((chunk ^ (r & 7)) * 16),
                  g_W16 + (size_t)r * YC + n0 + h * 64 + chunk * 8);
        }
    };

    issueB(0, 0); cp_commit();      // g0: A + B0
    issueB(1, 1); cp_commit();      // g1: B1

    #pragma unroll
    for (int t = 0; t < 4; ++t) {
        if (t < 3) cp_wait1(); else cp_wait0();
        __syncthreads();

        float acc[2][8][4];
        #pragma unroll
        for (int mt = 0; mt < 2; ++mt)
            #pragma unroll
            for (int nt = 0; nt < 8; ++nt)
                #pragma unroll
                for (int q = 0; q < 4; ++q) acc[mt][nt][q] = 0.0f;

        const uint32_t bB = bBase + (t & 1) * 16384 + wn * 8192;

        #pragma unroll
        for (int kt = 0; kt < 4; ++kt) {
            uint32_t a[2][4], b[8][2];
            #pragma unroll
            for (int mt = 0; mt < 2; ++mt) {
                const int rr = wm * 32 + mt * 16 + (lane & 15);
                const int cc = kt * 2 + (lane >> 4);
                ldsm_x4(a[mt], aBase + rr * 128 + ((cc ^ (rr & 7)) * 16));
            }
            #pragma unroll
            for (int p = 0; p < 4; ++p) {
                const int g = lane >> 3;
                const int row = kt * 16 + (g & 1) * 8 + (lane & 7);
                const int cchunk = p * 2 + (g >> 1);
                uint32_t bb[4];
                ldsm_x4t(bb, bB + row * 128 + ((cchunk ^ (row & 7)) * 16));
                b[2 * p][0] = bb[0]; b[2 * p][1] = bb[1];
                b[2 * p + 1][0] = bb[2]; b[2 * p + 1][1] = bb[3];
            }
            #pragma unroll
            for (int mt = 0; mt < 2; ++mt)
                #pragma unroll
                for (int nt = 0; nt < 8; ++nt)
                    mma16816(acc[mt][nt], a[mt], b[nt]);
        }

        __syncthreads();                       // all reads of buf t&1 complete
        if (t < 2) { issueB(t + 2, t & 1); cp_commit(); }

        // Store Y tile (fp16), overlapped with the async copy above.
        const int n0 = ng * 512 + t * 128;
        #pragma unroll
        for (int mt = 0; mt < 2; ++mt) {
            const int row = m0 + wm * 32 + mt * 16 + (lane >> 2);
            #pragma unroll
            for (int nt = 0; nt < 8; ++nt) {
                const int col = n0 + wn * 64 + nt * 8 + (lane & 3) * 2;
                const __half2 lo2 = __floats2half2_rn(acc[mt][nt][0], acc[mt][nt][1]);
                const __half2 hi2 = __floats2half2_rn(acc[mt][nt][2], acc[mt][nt][3]);
                *(__half2*)&g_Y16[(size_t)row * YC + col]       = lo2;
                *(__half2*)&g_Y16[(size_t)(row + 8) * YC + col] = hi2;
            }
        }
    }
}

// ---------------------------------------------------------------------------
// Gather: X[i,o] = sum over unmasked j of Y[j, cell(i,j)*64 + o]
// 64 threads = 2 warps; lane covers o = 2*lane, 2*lane+1 (half2 load):
// one 128B warp-load per entry. Warps stride entries by 2, 4-deep unroll.
// Writeout warp also accumulates BN partial sums via global atomics.
// ---------------------------------------------------------------------------
__global__ void __launch_bounds__(64) gather_kernel(const float* __restrict__ pos,
                                                    float* __restrict__ X) {
    __shared__ int list[NPED];
    __shared__ int cnt;
    __shared__ float2 xch[32];
    const int i = blockIdx.x, s = i >> 7, iloc = i & 127;
    const int tid = threadIdx.x, lane = tid & 31, w = tid >> 5;
    if (tid == 0) cnt = 0;
    __syncthreads();

    const float xi = pos[2 * i], yi = pos[2 * i + 1];
    const float tlx = xi - 1.0f, tly = yi + 1.0f, brx = xi + 1.0f, bry = yi - 1.0f;

    #pragma unroll
    for (int jj = 0; jj < 2; ++jj) {
        const int j = tid + jj * 64;
        const float xj = pos[2 * (s * NPED + j)];
        const float yj = pos[2 * (s * NPED + j) + 1];
        const bool m = (xj <= tlx) || (yj >= tly) || (xj >= brx) || (yj <= bry) || (j == iloc);
        if (!m) {
            const int gx = (int)floorf((xj - tlx) * 4.0f);
            const int gy = (int)floorf((tly - yj) * 4.0f);
            const int p = atomicAdd(&cnt, 1);
            list[p] = j * 8192 + (gx + 8 * gy) * 128;      // byte offset into Y frame
        }
    }
    __syncthreads();

    const char* Yf = (const char*)(g_Y16 + (size_t)s * NPED * YC) + lane * 4;
    const int n = cnt;
    float2 a0 = make_float2(0.f, 0.f), a1 = a0, a2 = a0, a3 = a0;
    int e = w;
    for (; e + 6 < n; e += 8) {
        const int o0 = list[e], o1 = list[e + 2], o2 = list[e + 4], o3 = list[e + 6];
        const float2 v0 = __half22float2(*(const __half2*)(Yf + o0));
        const float2 v1 = __half22float2(*(const __half2*)(Yf + o1));
        const float2 v2 = __half22float2(*(const __half2*)(Yf + o2));
        const float2 v3 = __half22float2(*(const __half2*)(Yf + o3));
        a0.x += v0.x; a0.y += v0.y;
        a1.x += v1.x; a1.y += v1.y;
        a2.x += v2.x; a2.y += v2.y;
        a3.x += v3.x; a3.y += v3.y;
    }
    for (; e < n; e += 2) {
        const float2 v = __half22float2(*(const __half2*)(Yf + list[e]));
        a0.x += v.x; a0.y += v.y;
    }
    float2 part;
    part.x = (a0.x + a1.x) + (a2.x + a3.x);
    part.y = (a0.y + a1.y) + (a2.y + a3.y);

    if (w == 1) xch[lane] = part;
    __syncthreads();
    if (w == 0) {
        const float2 t = xch[lane];
        part.x += t.x; part.y += t.y;
        *(float2*)&X[(size_t)i * NOUT + 2 * lane] = part;
        // BN partial sums (fire-and-forget REDG; 128 spread addresses)
        atomicAdd(&g_stat[2 * lane],          part.x);
        atomicAdd(&g_stat[2 * lane + 1],      part.y);
        atomicAdd(&g_stat[64 + 2 * lane],     part.x * part.x);
        atomicAdd(&g_stat[64 + 2 * lane + 1], part.y * part.y);
    }
}

// ---------------------------------------------------------------------------
// BN finalize: scale/shift from accumulated stats. Bias b cancels in (x-mean).
// ---------------------------------------------------------------------------
__global__ void red2_kernel(const float* __restrict__ gamma,
                            const float* __restrict__ beta) {
    const int o = threadIdx.x;   // 64
    const float s  = g_stat[o];
    const float s2 = g_stat[64 + o];
    const float mean = s * (1.0f / NROWS);
    const float var  = s2 * (1.0f / NROWS) - mean * mean;
    const float sc = rsqrtf(var + 1e-5f) * gamma[o];
    g_scale[o] = sc;
    g_shift[o] = beta[o] - mean * sc;
}

__global__ void bn_apply(float* __restrict__ X) {
    const int idx = blockIdx.x * blockDim.x + threadIdx.x;   // float4 index
    float4 v = ((float4*)X)[idx];
    const int o = (idx * 4) & 63;
    v.x = fmaxf(fmaf(v.x, g_scale[o],     g_shift[o]),     0.0f);
    v.y = fmaxf(fmaf(v.y, g_scale[o + 1], g_shift[o + 1]), 0.0f);
    v.z = fmaxf(fmaf(v.z, g_scale[o + 2], g_shift[o + 2]), 0.0f);
    v.w = fmaxf(fmaf(v.w, g_scale[o + 3], g_shift[o + 3]), 0.0f);
    ((float4*)X)[idx] = v;
}

// ---------------------------------------------------------------------------
extern "C" void kernel_launch(void* const* d_in, const int* in_sizes, int n_in,
                              void* d_out, int out_size) {
    const float* hs    = (const float*)d_in[0];   // hidden_states [4096,64]
    const float* pos   = (const float*)d_in[1];   // all_pos       [4096,2]
    const float* Wm    = (const float*)d_in[2];   // W             [4096,64]
    // d_in[3] = b: cancels inside BatchNorm
    const float* gamma = (const float*)d_in[4];
    const float* beta  = (const float*)d_in[5];
    float* X = (float*)d_out;

    prep_kernel<<<1280, 256>>>(Wm, hs);
    gemm_kernel<<<256, 256>>>();
    gather_kernel<<<4096, 64>>>(pos, X);
    red2_kernel<<<1, 64>>>(gamma, beta);
    bn_apply<<<256, 256>>>(X);
}

// round 11
// speedup vs baseline: 1.7265x; 1.7265x over previous
#include <cuda_runtime.h>
#include <cuda_fp16.h>
#include <math.h>
#include <stdint.h>

#define NPED  128
#define HD    64
#define NOUT  64
#define NROWS 4096
#define YC    4096      // Y columns = 64 cells * 64 out

// ---- scratch (no allocs allowed) ----
__device__ __align__(256) __half g_Y16[(size_t)NROWS * YC];    // 32 MB
__device__ __align__(256) __half g_W16[64 * YC];               // Wr: [h][c*64+o]
__device__ __align__(256) __half g_H16[NROWS * HD];            // hs fp16
__device__ float g_part[128 * 2 * NOUT];                       // BN partials
__device__ float g_scale[NOUT];
__device__ float g_shift[NOUT];

// ---------------- helpers ----------------
__device__ __forceinline__ uint32_t smem_u32(const void* p) {
    uint32_t a;
    asm("{ .reg .u64 t; cvta.to.shared.u64 t, %1; cvt.u32.u64 %0, t; }" : "=r"(a) : "l"(p));
    return a;
}
__device__ __forceinline__ void cpa16(uint32_t dst, const void* src) {
    asm volatile("cp.async.cg.shared.global [%0], [%1], 16;" :: "r"(dst), "l"(src));
}
__device__ __forceinline__ void cp_commit() {
    asm volatile("cp.async.commit_group;" ::: "memory");
}
__device__ __forceinline__ void cp_wait1() {
    asm volatile("cp.async.wait_group 1;" ::: "memory");
}
__device__ __forceinline__ void cp_wait0() {
    asm volatile("cp.async.wait_group 0;" ::: "memory");
}
__device__ __forceinline__ void ldsm_x4(uint32_t* a, uint32_t addr) {
    asm volatile("ldmatrix.sync.aligned.m8n8.x4.shared.b16 {%0,%1,%2,%3}, [%4];"
                 : "=r"(a[0]), "=r"(a[1]), "=r"(a[2]), "=r"(a[3]) : "r"(addr));
}
__device__ __forceinline__ void ldsm_x4t(uint32_t* b, uint32_t addr) {
    asm volatile("ldmatrix.sync.aligned.m8n8.x4.trans.shared.b16 {%0,%1,%2,%3}, [%4];"
                 : "=r"(b[0]), "=r"(b[1]), "=r"(b[2]), "=r"(b[3]) : "r"(addr));
}
__device__ __forceinline__ void mma16816(float* d, const uint32_t* a, const uint32_t* b) {
    asm volatile("mma.sync.aligned.m16n8k16.row.col.f32.f16.f16.f32 "
                 "{%0,%1,%2,%3}, {%4,%5,%6,%7}, {%8,%9}, {%0,%1,%2,%3};"
                 : "+f"(d[0]), "+f"(d[1]), "+f"(d[2]), "+f"(d[3])
                 : "r"(a[0]), "r"(a[1]), "r"(a[2]), "r"(a[3]), "r"(b[0]), "r"(b[1]));
}

// ---------------------------------------------------------------------------
// Prep: blocks [0,1024) convert W -> g_W16 (transposed layout); blocks
// [1024,1280) convert hs -> g_H16.
// ---------------------------------------------------------------------------
__global__ void prep_kernel(const float* __restrict__ W, const float* __restrict__ hs) {
    const int b = blockIdx.x, tid = threadIdx.x;
    if (b < 1024) {
        const int e = b * 256 + tid;                 // 262144 total
        const int widx = ((e >> 6) & 63) * YC + (e >> 12) * 64 + (e & 63);
        g_W16[widx] = __float2half_rn(W[e]);
    } else {
        const int e4 = (b - 1024) * 256 + tid;       // 65536 float4 groups
        const float4 v = ((const float4*)hs)[e4];
        __half2 a = __floats2half2_rn(v.x, v.y);
        __half2 c = __floats2half2_rn(v.z, v.w);
        uint2 w;
        w.x = *(uint32_t*)&a;
        w.y = *(uint32_t*)&c;
        ((uint2*)g_H16)[e4] = w;
    }
}

// ---------------------------------------------------------------------------
// GEMM: Y[4096, 4096] = hs16[4096, 64] @ W16[64, 4096], fp32 accum HMMA.
// Grid 256 = 32 mb x 8 ng. CTA: 256 threads, A stripe [128 x 64] loaded once,
// iterates 4 N-tiles of 128 with double-buffered cp.async B loads.
// ---------------------------------------------------------------------------
__global__ void __launch_bounds__(256) gemm_kernel() {
    __shared__ __align__(16) __half sA[128 * 64];           // 16 KB
    __shared__ __align__(16) __half sB[2][2][64 * 64];      // 32 KB: [buf][half]

    const int tid = threadIdx.x, lane = tid & 31, w = tid >> 5;
    const int wm = w & 3, wn = w >> 2;
    const int mb = blockIdx.x >> 3, ng = blockIdx.x & 7;
    const int m0 = mb * 128;

    const uint32_t aBase = smem_u32(sA);
    const uint32_t bBase = smem_u32(sB);

    // A: 1024 uint4, 4 per thread, swizzled.
    #pragma unroll
    for (int u = 0; u < 4; ++u) {
        const int idx = u * 256 + tid;
        const int r = idx >> 3, chunk = idx & 7;
        cpa16(aBase + r * 128 + ((chunk ^ (r & 7)) * 16),
              g_H16 + (size_t)(m0 + r) * HD + chunk * 8);
    }

    auto issueB = [&](int t, int buf) {
        const int n0 = ng * 512 + t * 128;
        #pragma unroll
        for (int u = 0; u < 4; ++u) {
            const int idx = u * 256 + tid;
            const int h = idx >> 9, i2 = idx & 511;
            const int r = i2 >> 3, chunk = i2 & 7;
            cpa16(bBase + buf * 16384 + h * 8192 + r * 128 + ((chunk ^ (r & 7)) * 16),
                  g_W16 + (size_t)r * YC + n0 + h * 64 + chunk * 8);
        }
    };

    issueB(0, 0); cp_commit();      // g0: A + B0
    issueB(1, 1); cp_commit();      // g1: B1

    #pragma unroll
    for (int t = 0; t < 4; ++t) {
        if (t < 3) cp_wait1(); else cp_wait0();
        __syncthreads();

        float acc[2][8][4];
        #pragma unroll
        for (int mt = 0; mt < 2; ++mt)
            #pragma unroll
            for (int nt = 0; nt < 8; ++nt)
                #pragma unroll
                for (int q = 0; q < 4; ++q) acc[mt][nt][q] = 0.0f;

        const uint32_t bB = bBase + (t & 1) * 16384 + wn * 8192;

        #pragma unroll
        for (int kt = 0; kt < 4; ++kt) {
            uint32_t a[2][4], b[8][2];
            #pragma unroll
            for (int mt = 0; mt < 2; ++mt) {
                const int rr = wm * 32 + mt * 16 + (lane & 15);
                const int cc = kt * 2 + (lane >> 4);
                ldsm_x4(a[mt], aBase + rr * 128 + ((cc ^ (rr & 7)) * 16));
            }
            #pragma unroll
            for (int p = 0; p < 4; ++p) {
                const int g = lane >> 3;
                const int row = kt * 16 + (g & 1) * 8 + (lane & 7);
                const int cchunk = p * 2 + (g >> 1);
                uint32_t bb[4];
                ldsm_x4t(bb, bB + row * 128 + ((cchunk ^ (row & 7)) * 16));
                b[2 * p][0] = bb[0]; b[2 * p][1] = bb[1];
                b[2 * p + 1][0] = bb[2]; b[2 * p + 1][1] = bb[3];
            }
            #pragma unroll
            for (int mt = 0; mt < 2; ++mt)
                #pragma unroll
                for (int nt = 0; nt < 8; ++nt)
                    mma16816(acc[mt][nt], a[mt], b[nt]);
        }

        __syncthreads();                       // all reads of buf t&1 complete
        if (t < 2) { issueB(t + 2, t & 1); cp_commit(); }

        // Store Y tile (fp16), overlapped with the async copy above.
        const int n0 = ng * 512 + t * 128;
        #pragma unroll
        for (int mt = 0; mt < 2; ++mt) {
            const int row = m0 + wm * 32 + mt * 16 + (lane >> 2);
            #pragma unroll
            for (int nt = 0; nt < 8; ++nt) {
                const int col = n0 + wn * 64 + nt * 8 + (lane & 3) * 2;
                const __half2 lo2 = __floats2half2_rn(acc[mt][nt][0], acc[mt][nt][1]);
                const __half2 hi2 = __floats2half2_rn(acc[mt][nt][2], acc[mt][nt][3]);
                *(__half2*)&g_Y16[(size_t)row * YC + col]       = lo2;
                *(__half2*)&g_Y16[(size_t)(row + 8) * YC + col] = hi2;
            }
        }
    }
}

// ---------------------------------------------------------------------------
// Gather: X[i,o] = sum over unmasked j of Y[j, cell(i,j)*64 + o]
// 64 threads = 2 warps; lane covers o = 2*lane, 2*lane+1 (half2 load):
// one 128B warp-load per entry. Warps stride entries by 2, 4-deep unroll.
// (R7 configuration — best measured: 9.4us. No global atomics.)
// ---------------------------------------------------------------------------
__global__ void __launch_bounds__(64) gather_kernel(const float* __restrict__ pos,
                                                    float* __restrict__ X) {
    __shared__ int list[NPED];
    __shared__ int cnt;
    __shared__ float2 xch[32];
    const int i = blockIdx.x, s = i >> 7, iloc = i & 127;
    const int tid = threadIdx.x, lane = tid & 31, w = tid >> 5;
    if (tid == 0) cnt = 0;
    __syncthreads();

    const float xi = pos[2 * i], yi = pos[2 * i + 1];
    const float tlx = xi - 1.0f, tly = yi + 1.0f, brx = xi + 1.0f, bry = yi - 1.0f;

    #pragma unroll
    for (int jj = 0; jj < 2; ++jj) {
        const int j = tid + jj * 64;
        const float xj = pos[2 * (s * NPED + j)];
        const float yj = pos[2 * (s * NPED + j) + 1];
        const bool m = (xj <= tlx) || (yj >= tly) || (xj >= brx) || (yj <= bry) || (j == iloc);
        if (!m) {
            const int gx = (int)floorf((xj - tlx) * 4.0f);
            const int gy = (int)floorf((tly - yj) * 4.0f);
            const int p = atomicAdd(&cnt, 1);
            list[p] = j * 8192 + (gx + 8 * gy) * 128;      // byte offset into Y frame
        }
    }
    __syncthreads();

    const char* Yf = (const char*)(g_Y16 + (size_t)s * NPED * YC) + lane * 4;
    const int n = cnt;
    float2 a0 = make_float2(0.f, 0.f), a1 = a0, a2 = a0, a3 = a0;
    int e = w;
    for (; e + 6 < n; e += 8) {
        const int o0 = list[e], o1 = list[e + 2], o2 = list[e + 4], o3 = list[e + 6];
        const float2 v0 = __half22float2(*(const __half2*)(Yf + o0));
        const float2 v1 = __half22float2(*(const __half2*)(Yf + o1));
        const float2 v2 = __half22float2(*(const __half2*)(Yf + o2));
        const float2 v3 = __half22float2(*(const __half2*)(Yf + o3));
        a0.x += v0.x; a0.y += v0.y;
        a1.x += v1.x; a1.y += v1.y;
        a2.x += v2.x; a2.y += v2.y;
        a3.x += v3.x; a3.y += v3.y;
    }
    for (; e < n; e += 2) {
        const float2 v = __half22float2(*(const __half2*)(Yf + list[e]));
        a0.x += v.x; a0.y += v.y;
    }
    float2 part;
    part.x = (a0.x + a1.x) + (a2.x + a3.x);
    part.y = (a0.y + a1.y) + (a2.y + a3.y);

    if (w == 1) xch[lane] = part;
    __syncthreads();
    if (w == 0) {
        const float2 t = xch[lane];
        part.x += t.x; part.y += t.y;
        *(float2*)&X[(size_t)i * NOUT + 2 * lane] = part;
    }
}

// ---------------------------------------------------------------------------
// BN stage 1: coalesced partial sums. Block b covers rows [b*32, b*32+32).
// ---------------------------------------------------------------------------
__global__ void red1_kernel(const float* __restrict__ X) {
    __shared__ float sm1[4][64], sm2[4][64];
    const int b = blockIdx.x, t = threadIdx.x;   // 128 blocks, 256 threads
    const int o = t & 63, g = t >> 6;
    float s = 0.0f, s2 = 0.0f;
    const float* base = X + (size_t)b * 32 * NOUT;
    #pragma unroll
    for (int r = g; r < 32; r += 4) {
        const float v = base[r * NOUT + o];
        s += v; s2 += v * v;
    }
    sm1[g][o] = s; sm2[g][o] = s2;
    __syncthreads();
    if (t < 64) {
        g_part[b * 128 + t]      = sm1[0][t] + sm1[1][t] + sm1[2][t] + sm1[3][t];
        g_part[b * 128 + 64 + t] = sm2[0][t] + sm2[1][t] + sm2[2][t] + sm2[3][t];
    }
}

// ---------------------------------------------------------------------------
// BN stage 2: finalize scale/shift. Bias b cancels in (x - mean).
// ---------------------------------------------------------------------------
__global__ void red2_kernel(const float* __restrict__ gamma,
                            const float* __restrict__ beta) {
    const int o = threadIdx.x;   // 64
    float s = 0.0f, s2 = 0.0f;
    #pragma unroll 4
    for (int p = 0; p < 128; ++p) {
        s  += g_part[p * 128 + o];
        s2 += g_part[p * 128 + 64 + o];
    }
    const float mean = s * (1.0f / NROWS);
    const float var  = s2 * (1.0f / NROWS) - mean * mean;
    const float sc = rsqrtf(var + 1e-5f) * gamma[o];
    g_scale[o] = sc;
    g_shift[o] = beta[o] - mean * sc;
}

__global__ void bn_apply(float* __restrict__ X) {
    const int idx = blockIdx.x * blockDim.x + threadIdx.x;   // float4 index
    float4 v = ((float4*)X)[idx];
    const int o = (idx * 4) & 63;
    v.x = fmaxf(fmaf(v.x, g_scale[o],     g_shift[o]),     0.0f);
    v.y = fmaxf(fmaf(v.y, g_scale[o + 1], g_shift[o + 1]), 0.0f);
    v.z = fmaxf(fmaf(v.z, g_scale[o + 2], g_shift[o + 2]), 0.0f);
    v.w = fmaxf(fmaf(v.w, g_scale[o + 3], g_shift[o + 3]), 0.0f);
    ((float4*)X)[idx] = v;
}

// ---------------------------------------------------------------------------
extern "C" void kernel_launch(void* const* d_in, const int* in_sizes, int n_in,
                              void* d_out, int out_size) {
    const float* hs    = (const float*)d_in[0];   // hidden_states [4096,64]
    const float* pos   = (const float*)d_in[1];   // all_pos       [4096,2]
    const float* Wm    = (const float*)d_in[2];   // W             [4096,64]
    // d_in[3] = b: cancels inside BatchNorm
    const float* gamma = (const float*)d_in[4];
    const float* beta  = (const float*)d_in[5];
    float* X = (float*)d_out;

    prep_kernel<<<1280, 256>>>(Wm, hs);
    gemm_kernel<<<256, 256>>>();
    gather_kernel<<<4096, 64>>>(pos, X);
    red1_kernel<<<128, 256>>>(X);
    red2_kernel<<<1, 64>>>(gamma, beta);
    bn_apply<<<256, 256>>>(X);
}

// round 12
// speedup vs baseline: 2.1616x; 1.2520x over previous
#include <cuda_runtime.h>
#include <cuda_fp16.h>
#include <math.h>
#include <stdint.h>

#define NPED  128
#define HD    64
#define NOUT  64
#define NROWS 4096
#define YC    4096      // Y columns = 64 cells * 64 out

// ---- scratch (no allocs allowed) ----
__device__ __align__(256) __half g_Y16[(size_t)NROWS * YC];    // 32 MB
__device__ __align__(256) __half g_W16[64 * YC];               // Wr: [h][c*64+o]
__device__ __align__(256) __half g_H16[NROWS * HD];            // hs fp16
__device__ float g_part2[32 * 128];                            // 32 replicas x (sum[64], sumsq[64])
__device__ float g_scale[NOUT];
__device__ float g_shift[NOUT];

// ---------------- helpers ----------------
__device__ __forceinline__ uint32_t smem_u32(const void* p) {
    uint32_t a;
    asm("{ .reg .u64 t; cvta.to.shared.u64 t, %1; cvt.u32.u64 %0, t; }" : "=r"(a) : "l"(p));
    return a;
}
__device__ __forceinline__ void cpa16(uint32_t dst, const void* src) {
    asm volatile("cp.async.cg.shared.global [%0], [%1], 16;" :: "r"(dst), "l"(src));
}
__device__ __forceinline__ void cp_commit() {
    asm volatile("cp.async.commit_group;" ::: "memory");
}
__device__ __forceinline__ void cp_wait1() {
    asm volatile("cp.async.wait_group 1;" ::: "memory");
}
__device__ __forceinline__ void cp_wait0() {
    asm volatile("cp.async.wait_group 0;" ::: "memory");
}
__device__ __forceinline__ void ldsm_x4(uint32_t* a, uint32_t addr) {
    asm volatile("ldmatrix.sync.aligned.m8n8.x4.shared.b16 {%0,%1,%2,%3}, [%4];"
                 : "=r"(a[0]), "=r"(a[1]), "=r"(a[2]), "=r"(a[3]) : "r"(addr));
}
__device__ __forceinline__ void ldsm_x4t(uint32_t* b, uint32_t addr) {
    asm volatile("ldmatrix.sync.aligned.m8n8.x4.trans.shared.b16 {%0,%1,%2,%3}, [%4];"
                 : "=r"(b[0]), "=r"(b[1]), "=r"(b[2]), "=r"(b[3]) : "r"(addr));
}
__device__ __forceinline__ void mma16816(float* d, const uint32_t* a, const uint32_t* b) {
    asm volatile("mma.sync.aligned.m16n8k16.row.col.f32.f16.f16.f32 "
                 "{%0,%1,%2,%3}, {%4,%5,%6,%7}, {%8,%9}, {%0,%1,%2,%3};"
                 : "+f"(d[0]), "+f"(d[1]), "+f"(d[2]), "+f"(d[3])
                 : "r"(a[0]), "r"(a[1]), "r"(a[2]), "r"(a[3]), "r"(b[0]), "r"(b[1]));
}

// ---------------------------------------------------------------------------
// Prep: blocks [0,1024) convert W -> g_W16 (transposed layout); blocks
// [1024,1280) convert hs -> g_H16. Block 0 zeroes the BN partial buffer.
// ---------------------------------------------------------------------------
__global__ void prep_kernel(const float* __restrict__ W, const float* __restrict__ hs) {
    const int b = blockIdx.x, tid = threadIdx.x;
    if (b == 0) {
        #pragma unroll
        for (int q = 0; q < 16; ++q) g_part2[q * 256 + tid] = 0.0f;
    }
    if (b < 1024) {
        const int e = b * 256 + tid;                 // 262144 total
        const int widx = ((e >> 6) & 63) * YC + (e >> 12) * 64 + (e & 63);
        g_W16[widx] = __float2half_rn(W[e]);
    } else {
        const int e4 = (b - 1024) * 256 + tid;       // 65536 float4 groups
        const float4 v = ((const float4*)hs)[e4];
        __half2 a = __floats2half2_rn(v.x, v.y);
        __half2 c = __floats2half2_rn(v.z, v.w);
        uint2 w;
        w.x = *(uint32_t*)&a;
        w.y = *(uint32_t*)&c;
        ((uint2*)g_H16)[e4] = w;
    }
}

// ---------------------------------------------------------------------------
// GEMM: Y[4096, 4096] = hs16[4096, 64] @ W16[64, 4096], fp32 accum HMMA.
// Grid 256 = 32 mb x 8 ng. CTA: 256 threads, A stripe [128 x 64] loaded once,
// iterates 4 N-tiles of 128 with double-buffered cp.async B loads.
// ---------------------------------------------------------------------------
__global__ void __launch_bounds__(256) gemm_kernel() {
    __shared__ __align__(16) __half sA[128 * 64];           // 16 KB
    __shared__ __align__(16) __half sB[2][2][64 * 64];      // 32 KB: [buf][half]

    const int tid = threadIdx.x, lane = tid & 31, w = tid >> 5;
    const int wm = w & 3, wn = w >> 2;
    const int mb = blockIdx.x >> 3, ng = blockIdx.x & 7;
    const int m0 = mb * 128;

    const uint32_t aBase = smem_u32(sA);
    const uint32_t bBase = smem_u32(sB);

    // A: 1024 uint4, 4 per thread, swizzled.
    #pragma unroll
    for (int u = 0; u < 4; ++u) {
        const int idx = u * 256 + tid;
        const int r = idx >> 3, chunk = idx & 7;
        cpa16(aBase + r * 128 + ((chunk ^ (r & 7)) * 16),
              g_H16 + (size_t)(m0 + r) * HD + chunk * 8);
    }

    auto issueB = [&](int t, int buf) {
        const int n0 = ng * 512 + t * 128;
        #pragma unroll
        for (int u = 0; u < 4; ++u) {
            const int idx = u * 256 + tid;
            const int h = idx >> 9, i2 = idx & 511;
            const int r = i2 >> 3, chunk = i2 & 7;
            cpa16(bBase + buf * 16384 + h * 8192 + r * 128 + ((chunk ^ (r & 7)) * 16),
                  g_W16 + (size_t)r * YC + n0 + h * 64 + chunk * 8);
        }
    };

    issueB(0, 0); cp_commit();      // g0: A + B0
    issueB(1, 1); cp_commit();      // g1: B1

    #pragma unroll
    for (int t = 0; t < 4; ++t) {
        if (t < 3) cp_wait1(); else cp_wait0();
        __syncthreads();

        float acc[2][8][4];
        #pragma unroll
        for (int mt = 0; mt < 2; ++mt)
            #pragma unroll
            for (int nt = 0; nt < 8; ++nt)
                #pragma unroll
                for (int q = 0; q < 4; ++q) acc[mt][nt][q] = 0.0f;

        const uint32_t bB = bBase + (t & 1) * 16384 + wn * 8192;

        #pragma unroll
        for (int kt = 0; kt < 4; ++kt) {
            uint32_t a[2][4], b[8][2];
            #pragma unroll
            for (int mt = 0; mt < 2; ++mt) {
                const int rr = wm * 32 + mt * 16 + (lane & 15);
                const int cc = kt * 2 + (lane >> 4);
                ldsm_x4(a[mt], aBase + rr * 128 + ((cc ^ (rr & 7)) * 16));
            }
            #pragma unroll
            for (int p = 0; p < 4; ++p) {
                const int g = lane >> 3;
                const int row = kt * 16 + (g & 1) * 8 + (lane & 7);
                const int cchunk = p * 2 + (g >> 1);
                uint32_t bb[4];
                ldsm_x4t(bb, bB + row * 128 + ((cchunk ^ (row & 7)) * 16));
                b[2 * p][0] = bb[0]; b[2 * p][1] = bb[1];
                b[2 * p + 1][0] = bb[2]; b[2 * p + 1][1] = bb[3];
            }
            #pragma unroll
            for (int mt = 0; mt < 2; ++mt)
                #pragma unroll
                for (int nt = 0; nt < 8; ++nt)
                    mma16816(acc[mt][nt], a[mt], b[nt]);
        }

        __syncthreads();                       // all reads of buf t&1 complete
        if (t < 2) { issueB(t + 2, t & 1); cp_commit(); }

        // Store Y tile (fp16), overlapped with the async copy above.
        const int n0 = ng * 512 + t * 128;
        #pragma unroll
        for (int mt = 0; mt < 2; ++mt) {
            const int row = m0 + wm * 32 + mt * 16 + (lane >> 2);
            #pragma unroll
            for (int nt = 0; nt < 8; ++nt) {
                const int col = n0 + wn * 64 + nt * 8 + (lane & 3) * 2;
                const __half2 lo2 = __floats2half2_rn(acc[mt][nt][0], acc[mt][nt][1]);
                const __half2 hi2 = __floats2half2_rn(acc[mt][nt][2], acc[mt][nt][3]);
                *(__half2*)&g_Y16[(size_t)row * YC + col]       = lo2;
                *(__half2*)&g_Y16[(size_t)(row + 8) * YC + col] = hi2;
            }
        }
    }
}

// ---------------------------------------------------------------------------
// Gather: X[i,o] = sum over unmasked j of Y[j, cell(i,j)*64 + o]
// 64 threads = 2 warps; lane covers o = 2*lane, 2*lane+1 (half2 load):
// one 128B warp-load per entry. Warps stride entries by 2, 4-deep unroll.
// Writeout warp adds BN partials into replica (i & 31): 128 CTAs/address.
// ---------------------------------------------------------------------------
__global__ void __launch_bounds__(64) gather_kernel(const float* __restrict__ pos,
                                                    float* __restrict__ X) {
    __shared__ int list[NPED];
    __shared__ int cnt;
    __shared__ float2 xch[32];
    const int i = blockIdx.x, s = i >> 7, iloc = i & 127;
    const int tid = threadIdx.x, lane = tid & 31, w = tid >> 5;
    if (tid == 0) cnt = 0;
    __syncthreads();

    const float xi = pos[2 * i], yi = pos[2 * i + 1];
    const float tlx = xi - 1.0f, tly = yi + 1.0f, brx = xi + 1.0f, bry = yi - 1.0f;

    #pragma unroll
    for (int jj = 0; jj < 2; ++jj) {
        const int j = tid + jj * 64;
        const float xj = pos[2 * (s * NPED + j)];
        const float yj = pos[2 * (s * NPED + j) + 1];
        const bool m = (xj <= tlx) || (yj >= tly) || (xj >= brx) || (yj <= bry) || (j == iloc);
        if (!m) {
            const int gx = (int)floorf((xj - tlx) * 4.0f);
            const int gy = (int)floorf((tly - yj) * 4.0f);
            const int p = atomicAdd(&cnt, 1);
            list[p] = j * 8192 + (gx + 8 * gy) * 128;      // byte offset into Y frame
        }
    }
    __syncthreads();

    const char* Yf = (const char*)(g_Y16 + (size_t)s * NPED * YC) + lane * 4;
    const int n = cnt;
    float2 a0 = make_float2(0.f, 0.f), a1 = a0, a2 = a0, a3 = a0;
    int e = w;
    for (; e + 6 < n; e += 8) {
        const int o0 = list[e], o1 = list[e + 2], o2 = list[e + 4], o3 = list[e + 6];
        const float2 v0 = __half22float2(*(const __half2*)(Yf + o0));
        const float2 v1 = __half22float2(*(const __half2*)(Yf + o1));
        const float2 v2 = __half22float2(*(const __half2*)(Yf + o2));
        const float2 v3 = __half22float2(*(const __half2*)(Yf + o3));
        a0.x += v0.x; a0.y += v0.y;
        a1.x += v1.x; a1.y += v1.y;
        a2.x += v2.x; a2.y += v2.y;
        a3.x += v3.x; a3.y += v3.y;
    }
    for (; e < n; e += 2) {
        const float2 v = __half22float2(*(const __half2*)(Yf + list[e]));
        a0.x += v.x; a0.y += v.y;
    }
    float2 part;
    part.x = (a0.x + a1.x) + (a2.x + a3.x);
    part.y = (a0.y + a1.y) + (a2.y + a3.y);

    if (w == 1) xch[lane] = part;
    __syncthreads();
    if (w == 0) {
        const float2 t = xch[lane];
        part.x += t.x; part.y += t.y;
        *(float2*)&X[(size_t)i * NOUT + 2 * lane] = part;
        // BN partials into replica (i & 31): fire-and-forget, low contention.
        float* rep = g_part2 + (i & 31) * 128;
        atomicAdd(rep + 2 * lane,          part.x);
        atomicAdd(rep + 2 * lane + 1,      part.y);
        atomicAdd(rep + 64 + 2 * lane,     part.x * part.x);
        atomicAdd(rep + 64 + 2 * lane + 1, part.y * part.y);
    }
}

// ---------------------------------------------------------------------------
// BN finalize: sum 32 replicas (fixed order), compute scale/shift.
// Bias b cancels in (x - mean).
// ---------------------------------------------------------------------------
__global__ void red2_kernel(const float* __restrict__ gamma,
                            const float* __restrict__ beta) {
    const int o = threadIdx.x;   // 64
    float s = 0.0f, s2 = 0.0f;
    #pragma unroll
    for (int r = 0; r < 32; ++r) {
        s  += g_part2[r * 128 + o];
        s2 += g_part2[r * 128 + 64 + o];
    }
    const float mean = s * (1.0f / NROWS);
    const float var  = s2 * (1.0f / NROWS) - mean * mean;
    const float sc = rsqrtf(var + 1e-5f) * gamma[o];
    g_scale[o] = sc;
    g_shift[o] = beta[o] - mean * sc;
}

__global__ void bn_apply(float* __restrict__ X) {
    const int idx = blockIdx.x * blockDim.x + threadIdx.x;   // float4 index
    float4 v = ((float4*)X)[idx];
    const int o = (idx * 4) & 63;
    v.x = fmaxf(fmaf(v.x, g_scale[o],     g_shift[o]),     0.0f);
    v.y = fmaxf(fmaf(v.y, g_scale[o + 1], g_shift[o + 1]), 0.0f);
    v.z = fmaxf(fmaf(v.z, g_scale[o + 2], g_shift[o + 2]), 0.0f);
    v.w = fmaxf(fmaf(v.w, g_scale[o + 3], g_shift[o + 3]), 0.0f);
    ((float4*)X)[idx] = v;
}

// ---------------------------------------------------------------------------
extern "C" void kernel_launch(void* const* d_in, const int* in_sizes, int n_in,
                              void* d_out, int out_size) {
    const float* hs    = (const float*)d_in[0];   // hidden_states [4096,64]
    const float* pos   = (const float*)d_in[1];   // all_pos       [4096,2]
    const float* Wm    = (const float*)d_in[2];   // W             [4096,64]
    // d_in[3] = b: cancels inside BatchNorm
    const float* gamma = (const float*)d_in[4];
    const float* beta  = (const float*)d_in[5];
    float* X = (float*)d_out;

    prep_kernel<<<1280, 256>>>(Wm, hs);
    gemm_kernel<<<256, 256>>>();
    gather_kernel<<<4096, 64>>>(pos, X);
    red2_kernel<<<1, 64>>>(gamma, beta);
    bn_apply<<<256, 256>>>(X);
}

// round 13
// speedup vs baseline: 2.3348x; 1.0801x over previous
#include <cuda_runtime.h>
#include <cuda_fp16.h>
#include <math.h>
#include <stdint.h>

#define NPED  128
#define HD    64
#define NOUT  64
#define NROWS 4096
#define YC    4096      // Y columns = 64 cells * 64 out

// ---- scratch (no allocs allowed) ----
__device__ __align__(256) __half g_Y16[(size_t)NROWS * YC];    // 32 MB
__device__ __align__(256) __half g_W16[64 * YC];               // Wr: [h][c*64+o]
__device__ __align__(256) __half g_H16[NROWS * HD];            // hs fp16
__device__ float g_part2[32 * 128];                            // 32 replicas x (sum[64], sumsq[64])

// ---------------- helpers ----------------
__device__ __forceinline__ uint32_t smem_u32(const void* p) {
    uint32_t a;
    asm("{ .reg .u64 t; cvta.to.shared.u64 t, %1; cvt.u32.u64 %0, t; }" : "=r"(a) : "l"(p));
    return a;
}
__device__ __forceinline__ void cpa16(uint32_t dst, const void* src) {
    asm volatile("cp.async.cg.shared.global [%0], [%1], 16;" :: "r"(dst), "l"(src));
}
__device__ __forceinline__ void cp_commit() {
    asm volatile("cp.async.commit_group;" ::: "memory");
}
__device__ __forceinline__ void cp_wait1() {
    asm volatile("cp.async.wait_group 1;" ::: "memory");
}
__device__ __forceinline__ void cp_wait0() {
    asm volatile("cp.async.wait_group 0;" ::: "memory");
}
__device__ __forceinline__ void ldsm_x4(uint32_t* a, uint32_t addr) {
    asm volatile("ldmatrix.sync.aligned.m8n8.x4.shared.b16 {%0,%1,%2,%3}, [%4];"
                 : "=r"(a[0]), "=r"(a[1]), "=r"(a[2]), "=r"(a[3]) : "r"(addr));
}
__device__ __forceinline__ void ldsm_x4t(uint32_t* b, uint32_t addr) {
    asm volatile("ldmatrix.sync.aligned.m8n8.x4.trans.shared.b16 {%0,%1,%2,%3}, [%4];"
                 : "=r"(b[0]), "=r"(b[1]), "=r"(b[2]), "=r"(b[3]) : "r"(addr));
}
__device__ __forceinline__ void mma16816(float* d, const uint32_t* a, const uint32_t* b) {
    asm volatile("mma.sync.aligned.m16n8k16.row.col.f32.f16.f16.f32 "
                 "{%0,%1,%2,%3}, {%4,%5,%6,%7}, {%8,%9}, {%0,%1,%2,%3};"
                 : "+f"(d[0]), "+f"(d[1]), "+f"(d[2]), "+f"(d[3])
                 : "r"(a[0]), "r"(a[1]), "r"(a[2]), "r"(a[3]), "r"(b[0]), "r"(b[1]));
}

// ---------------------------------------------------------------------------
// Prep: blocks [0,1024) convert W -> g_W16 (transposed layout); blocks
// [1024,1280) convert hs -> g_H16. Block 0 zeroes the BN partial buffer.
// ---------------------------------------------------------------------------
__global__ void prep_kernel(const float* __restrict__ W, const float* __restrict__ hs) {
    const int b = blockIdx.x, tid = threadIdx.x;
    if (b == 0) {
        #pragma unroll
        for (int q = 0; q < 16; ++q) g_part2[q * 256 + tid] = 0.0f;
    }
    if (b < 1024) {
        const int e = b * 256 + tid;                 // 262144 total
        const int widx = ((e >> 6) & 63) * YC + (e >> 12) * 64 + (e & 63);
        g_W16[widx] = __float2half_rn(W[e]);
    } else {
        const int e4 = (b - 1024) * 256 + tid;       // 65536 float4 groups
        const float4 v = ((const float4*)hs)[e4];
        __half2 a = __floats2half2_rn(v.x, v.y);
        __half2 c = __floats2half2_rn(v.z, v.w);
        uint2 w;
        w.x = *(uint32_t*)&a;
        w.y = *(uint32_t*)&c;
        ((uint2*)g_H16)[e4] = w;
    }
}

// ---------------------------------------------------------------------------
// GEMM: Y[4096, 4096] = hs16[4096, 64] @ W16[64, 4096], fp32 accum HMMA.
// Grid 256 = 32 mb x 8 ng. CTA: 256 threads, A stripe [128 x 64] loaded once,
// iterates 4 N-tiles of 128 with double-buffered cp.async B loads.
// ---------------------------------------------------------------------------
__global__ void __launch_bounds__(256) gemm_kernel() {
    __shared__ __align__(16) __half sA[128 * 64];           // 16 KB
    __shared__ __align__(16) __half sB[2][2][64 * 64];      // 32 KB: [buf][half]

    const int tid = threadIdx.x, lane = tid & 31, w = tid >> 5;
    const int wm = w & 3, wn = w >> 2;
    const int mb = blockIdx.x >> 3, ng = blockIdx.x & 7;
    const int m0 = mb * 128;

    const uint32_t aBase = smem_u32(sA);
    const uint32_t bBase = smem_u32(sB);

    // A: 1024 uint4, 4 per thread, swizzled.
    #pragma unroll
    for (int u = 0; u < 4; ++u) {
        const int idx = u * 256 + tid;
        const int r = idx >> 3, chunk = idx & 7;
        cpa16(aBase + r * 128 + ((chunk ^ (r & 7)) * 16),
              g_H16 + (size_t)(m0 + r) * HD + chunk * 8);
    }

    auto issueB = [&](int t, int buf) {
        const int n0 = ng * 512 + t * 128;
        #pragma unroll
        for (int u = 0; u < 4; ++u) {
            const int idx = u * 256 + tid;
            const int h = idx >> 9, i2 = idx & 511;
            const int r = i2 >> 3, chunk = i2 & 7;
            cpa16(bBase + buf * 16384 + h * 8192 + r * 128 + ((chunk ^ (r & 7)) * 16),
                  g_W16 + (size_t)r * YC + n0 + h * 64 + chunk * 8);
        }
    };

    issueB(0, 0); cp_commit();      // g0: A + B0
    issueB(1, 1); cp_commit();      // g1: B1

    #pragma unroll
    for (int t = 0; t < 4; ++t) {
        if (t < 3) cp_wait1(); else cp_wait0();
        __syncthreads();

        float acc[2][8][4];
        #pragma unroll
        for (int mt = 0; mt < 2; ++mt)
            #pragma unroll
            for (int nt = 0; nt < 8; ++nt)
                #pragma unroll
                for (int q = 0; q < 4; ++q) acc[mt][nt][q] = 0.0f;

        const uint32_t bB = bBase + (t & 1) * 16384 + wn * 8192;

        #pragma unroll
        for (int kt = 0; kt < 4; ++kt) {
            uint32_t a[2][4], b[8][2];
            #pragma unroll
            for (int mt = 0; mt < 2; ++mt) {
                const int rr = wm * 32 + mt * 16 + (lane & 15);
                const int cc = kt * 2 + (lane >> 4);
                ldsm_x4(a[mt], aBase + rr * 128 + ((cc ^ (rr & 7)) * 16));
            }
            #pragma unroll
            for (int p = 0; p < 4; ++p) {
                const int g = lane >> 3;
                const int row = kt * 16 + (g & 1) * 8 + (lane & 7);
                const int cchunk = p * 2 + (g >> 1);
                uint32_t bb[4];
                ldsm_x4t(bb, bB + row * 128 + ((cchunk ^ (row & 7)) * 16));
                b[2 * p][0] = bb[0]; b[2 * p][1] = bb[1];
                b[2 * p + 1][0] = bb[2]; b[2 * p + 1][1] = bb[3];
            }
            #pragma unroll
            for (int mt = 0; mt < 2; ++mt)
                #pragma unroll
                for (int nt = 0; nt < 8; ++nt)
                    mma16816(acc[mt][nt], a[mt], b[nt]);
        }

        __syncthreads();                       // all reads of buf t&1 complete
        if (t < 2) { issueB(t + 2, t & 1); cp_commit(); }

        // Store Y tile (fp16), overlapped with the async copy above.
        const int n0 = ng * 512 + t * 128;
        #pragma unroll
        for (int mt = 0; mt < 2; ++mt) {
            const int row = m0 + wm * 32 + mt * 16 + (lane >> 2);
            #pragma unroll
            for (int nt = 0; nt < 8; ++nt) {
                const int col = n0 + wn * 64 + nt * 8 + (lane & 3) * 2;
                const __half2 lo2 = __floats2half2_rn(acc[mt][nt][0], acc[mt][nt][1]);
                const __half2 hi2 = __floats2half2_rn(acc[mt][nt][2], acc[mt][nt][3]);
                *(__half2*)&g_Y16[(size_t)row * YC + col]       = lo2;
                *(__half2*)&g_Y16[(size_t)(row + 8) * YC + col] = hi2;
            }
        }
    }
}

// ---------------------------------------------------------------------------
// Gather: X[i,o] = sum over unmasked j of Y[j, cell(i,j)*64 + o]
// 64 threads = 2 warps; lane covers o = 2*lane, 2*lane+1 (half2 load):
// one 128B warp-load per entry. Warps stride entries by 2, 4-deep unroll.
// Writeout warp adds BN partials into replica (i & 31): 128 CTAs/address.
// ---------------------------------------------------------------------------
__global__ void __launch_bounds__(64) gather_kernel(const float* __restrict__ pos,
                                                    float* __restrict__ X) {
    __shared__ int list[NPED];
    __shared__ int cnt;
    __shared__ float2 xch[32];
    const int i = blockIdx.x, s = i >> 7, iloc = i & 127;
    const int tid = threadIdx.x, lane = tid & 31, w = tid >> 5;
    if (tid == 0) cnt = 0;
    __syncthreads();

    const float xi = pos[2 * i], yi = pos[2 * i + 1];
    const float tlx = xi - 1.0f, tly = yi + 1.0f, brx = xi + 1.0f, bry = yi - 1.0f;

    #pragma unroll
    for (int jj = 0; jj < 2; ++jj) {
        const int j = tid + jj * 64;
        const float xj = pos[2 * (s * NPED + j)];
        const float yj = pos[2 * (s * NPED + j) + 1];
        const bool m = (xj <= tlx) || (yj >= tly) || (xj >= brx) || (yj <= bry) || (j == iloc);
        if (!m) {
            const int gx = (int)floorf((xj - tlx) * 4.0f);
            const int gy = (int)floorf((tly - yj) * 4.0f);
            const int p = atomicAdd(&cnt, 1);
            list[p] = j * 8192 + (gx + 8 * gy) * 128;      // byte offset into Y frame
        }
    }
    __syncthreads();

    const char* Yf = (const char*)(g_Y16 + (size_t)s * NPED * YC) + lane * 4;
    const int n = cnt;
    float2 a0 = make_float2(0.f, 0.f), a1 = a0, a2 = a0, a3 = a0;
    int e = w;
    for (; e + 6 < n; e += 8) {
        const int o0 = list[e], o1 = list[e + 2], o2 = list[e + 4], o3 = list[e + 6];
        const float2 v0 = __half22float2(*(const __half2*)(Yf + o0));
        const float2 v1 = __half22float2(*(const __half2*)(Yf + o1));
        const float2 v2 = __half22float2(*(const __half2*)(Yf + o2));
        const float2 v3 = __half22float2(*(const __half2*)(Yf + o3));
        a0.x += v0.x; a0.y += v0.y;
        a1.x += v1.x; a1.y += v1.y;
        a2.x += v2.x; a2.y += v2.y;
        a3.x += v3.x; a3.y += v3.y;
    }
    for (; e < n; e += 2) {
        const float2 v = __half22float2(*(const __half2*)(Yf + list[e]));
        a0.x += v.x; a0.y += v.y;
    }
    float2 part;
    part.x = (a0.x + a1.x) + (a2.x + a3.x);
    part.y = (a0.y + a1.y) + (a2.y + a3.y);

    if (w == 1) xch[lane] = part;
    __syncthreads();
    if (w == 0) {
        const float2 t = xch[lane];
        part.x += t.x; part.y += t.y;
        *(float2*)&X[(size_t)i * NOUT + 2 * lane] = part;
        // BN partials into replica (i & 31): fire-and-forget, low contention.
        float* rep = g_part2 + (i & 31) * 128;
        atomicAdd(rep + 2 * lane,          part.x);
        atomicAdd(rep + 2 * lane + 1,      part.y);
        atomicAdd(rep + 64 + 2 * lane,     part.x * part.x);
        atomicAdd(rep + 64 + 2 * lane + 1, part.y * part.y);
    }
}

// ---------------------------------------------------------------------------
// BN finalize + apply + ReLU, fused. Each of 128 blocks redundantly reduces
// the 32-replica partial buffer (256 thr x 16 strided loads, MLP 16), builds
// scale/shift in smem, then applies to its slice (2 float4 per thread).
// Bias b cancels in (x - mean).
// ---------------------------------------------------------------------------
__global__ void __launch_bounds__(256) bn_apply(float* __restrict__ X,
                                                const float* __restrict__ gamma,
                                                const float* __restrict__ beta) {
    __shared__ float sm[256];
    __shared__ float stat[128];
    __shared__ float ssc[64], ssh[64];
    const int t = threadIdx.x;

    // Thread t sums positions (t & 127) across replicas (t>>7) + 2k.
    float s = 0.0f;
    #pragma unroll
    for (int k = 0; k < 16; ++k) s += g_part2[t + 256 * k];
    sm[t] = s;
    __syncthreads();
    if (t < 128) stat[t] = sm[t] + sm[t + 128];
    __syncthreads();
    if (t < 64) {
        const float mean = stat[t] * (1.0f / NROWS);
        const float var  = stat[64 + t] * (1.0f / NROWS) - mean * mean;
        const float sc = rsqrtf(var + 1e-5f) * gamma[t];
        ssc[t] = sc;
        ssh[t] = beta[t] - mean * sc;
    }
    __syncthreads();

    #pragma unroll
    for (int q = 0; q < 2; ++q) {
        const int idx = blockIdx.x * 512 + q * 256 + t;      // float4 index
        float4 v = ((float4*)X)[idx];
        const int o = (idx * 4) & 63;
        v.x = fmaxf(fmaf(v.x, ssc[o],     ssh[o]),     0.0f);
        v.y = fmaxf(fmaf(v.y, ssc[o + 1], ssh[o + 1]), 0.0f);
        v.z = fmaxf(fmaf(v.z, ssc[o + 2], ssh[o + 2]), 0.0f);
        v.w = fmaxf(fmaf(v.w, ssc[o + 3], ssh[o + 3]), 0.0f);
        ((float4*)X)[idx] = v;
    }
}

// ---------------------------------------------------------------------------
extern "C" void kernel_launch(void* const* d_in, const int* in_sizes, int n_in,
                              void* d_out, int out_size) {
    const float* hs    = (const float*)d_in[0];   // hidden_states [4096,64]
    const float* pos   = (const float*)d_in[1];   // all_pos       [4096,2]
    const float* Wm    = (const float*)d_in[2];   // W             [4096,64]
    // d_in[3] = b: cancels inside BatchNorm
    const float* gamma = (const float*)d_in[4];
    const float* beta  = (const float*)d_in[5];
    float* X = (float*)d_out;

    prep_kernel<<<1280, 256>>>(Wm, hs);
    gemm_kernel<<<256, 256>>>();
    gather_kernel<<<4096, 64>>>(pos, X);
    bn_apply<<<128, 256>>>(X, gamma, beta);
}